// round 10
// baseline (speedup 1.0000x reference)
#include <cuda_runtime.h>

#define NQ    12
#define DEPTH 6
#define TPB   64

typedef unsigned int u32;

// ---------------------------------------------------------------------------
// Wire q <-> flat-index bit (11-q). CNOT ring tracked as GF(2)-linear storage
// permutation; Q_d = F^d columns precomputed (with smem swizzle composed in).
// ---------------------------------------------------------------------------
__host__ __device__ constexpr u32 Fmap(u32 b) {
    for (int g = 11; g >= 0; --g) {
        int c = 11 - g, t = (c + 11) % NQ;
        b ^= ((b >> c) & 1u) << t;
    }
    return b;
}
__host__ __device__ constexpr u32 Finvmap(u32 b) {
    for (int g = 0; g < NQ; ++g) {
        int c = 11 - g, t = (c + 11) % NQ;
        b ^= ((b >> c) & 1u) << t;
    }
    return b;
}
__host__ __device__ constexpr u32 swz(u32 x) { return x ^ ((x >> 5) & 31u); }

struct Tabs {
    u32 q[DEPTH][NQ];  // swizzled columns of Q_d = F^d
    u32 finv[NQ];      // columns of F^{-1} (logical space, for final weights)
};
__host__ __device__ constexpr Tabs mk_tabs() {
    Tabs t{};
    u32 raw[NQ] = {};
    for (int j = 0; j < NQ; ++j) { raw[j] = 1u << j; t.q[0][j] = swz(raw[j]); }
    for (int d = 1; d < DEPTH; ++d)
        for (int j = 0; j < NQ; ++j) { raw[j] = Fmap(raw[j]); t.q[d][j] = swz(raw[j]); }
    for (int j = 0; j < NQ; ++j) t.finv[j] = Finvmap(1u << j);
    return t;
}
__constant__ Tabs TAB = mk_tabs();

// 2 passes/layer, 6 register gate-bits each; 6 filler bits from tid.
__constant__ int DIRS6[2][6] = {{0,1,2,3,4,5},{6,7,8,9,10,11}};
__constant__ int FILL6[2][6] = {{6,7,8,9,10,11},{0,1,2,3,4,5}};

__device__ __forceinline__ float2 cmul(float2 a, float2 b) {
    return make_float2(fmaf(a.x, b.x, -a.y * b.y), fmaf(a.x, b.y, a.y * b.x));
}

__global__ void __launch_bounds__(TPB)
qsim_kernel(const float* __restrict__ inp, const float* __restrict__ wp,
            float* __restrict__ out)
{
    __shared__ float2 sv[1 << NQ];               // 32 KB state (AoS re,im)
    __shared__ float2 gms[DEPTH * NQ * 2];       // m00,m01 per gate (SU(2))
    __shared__ float2 vtab[NQ][2];               // per-qubit prep 2-vectors
    __shared__ float  red[TPB / 32];

    const int t   = threadIdx.x;                 // 6 bits
    const int bid = blockIdx.x;

    // ---- per-block prep ----------------------------------------------------
    if (t < NQ) {
        // fold encode RY(x) with layer-1 Rot into one complex 2-vector/qubit
        float x = inp[bid * NQ + (11 - t)];      // bit t <- wire 11-t
        float sx, cx; sincosf(0.5f * x, &sx, &cx);
        int wo = (11 - t) * 3;                   // w[0][wire]
        float phi = wp[wo + 0], th = wp[wo + 1], om = wp[wo + 2];
        float st, ct; sincosf(0.5f * th, &st, &ct);
        float sa, ca; sincosf(0.5f * (phi + om), &sa, &ca);
        float sb, cb; sincosf(0.5f * (phi - om), &sb, &cb);
        float2 m00 = make_float2( ct * ca, -ct * sa);
        float2 m01 = make_float2(-st * cb, -st * sb);
        float2 m10 = make_float2( st * cb, -st * sb);   // = -conj(m01)
        float2 m11 = make_float2( ct * ca,  ct * sa);   // =  conj(m00)
        vtab[t][0] = make_float2(fmaf(m00.x, cx, m01.x * sx), fmaf(m00.y, cx, m01.y * sx));
        vtab[t][1] = make_float2(fmaf(m10.x, cx, m11.x * sx), fmaf(m10.y, cx, m11.y * sx));
    }
    for (int i = NQ + t; i < DEPTH * NQ; i += TPB) {   // layers 2..6 gates
        int d = i / NQ, m = i % NQ;              // m = bit index, wire = 11-m
        int wo = (d * NQ + (11 - m)) * 3;
        float phi = wp[wo + 0], th = wp[wo + 1], om = wp[wo + 2];
        float st, ct; sincosf(0.5f * th, &st, &ct);
        float sa, ca; sincosf(0.5f * (phi + om), &sa, &ca);
        float sb, cb; sincosf(0.5f * (phi - om), &sb, &cb);
        gms[i * 2 + 0] = make_float2( ct * ca, -ct * sa);   // m00
        gms[i * 2 + 1] = make_float2(-st * cb, -st * sb);   // m01
    }
    __syncthreads();

    // ---- prep pass: build psi_1 (encode + layer-1 Rot) and store ----------
    {
        const u32* qc = TAB.q[0];
        u32 pb = 0;
        #pragma unroll
        for (int j = 0; j < 6; ++j)
            if ((t >> j) & 1) pb ^= qc[FILL6[0][j]];
        u32 qd[6];
        #pragma unroll
        for (int k = 0; k < 6; ++k) qd[k] = qc[DIRS6[0][k]];

        float2 f = vtab[FILL6[0][0]][t & 1];
        #pragma unroll
        for (int j = 1; j < 6; ++j) f = cmul(f, vtab[FILL6[0][j]][(t >> j) & 1]);
        float2 v[64]; v[0] = f;
        #pragma unroll
        for (int j = 0; j < 6; ++j) {
            #pragma unroll
            for (int k = 0; k < (1 << j); ++k) {
                float2 lo = v[k];
                v[k]            = cmul(lo, vtab[DIRS6[0][j]][0]);
                v[k + (1 << j)] = cmul(lo, vtab[DIRS6[0][j]][1]);
            }
        }
        #pragma unroll
        for (int c = 0; c < 64; ++c) {
            u32 a = pb;
            if (c & 1)  a ^= qd[0];
            if (c & 2)  a ^= qd[1];
            if (c & 4)  a ^= qd[2];
            if (c & 8)  a ^= qd[3];
            if (c & 16) a ^= qd[4];
            if (c & 32) a ^= qd[5];
            sv[a] = v[c];
        }
        __syncthreads();
    }

    float acc = 0.f;

    // ---- variational layers 2..6: 2 passes each, 6 gates/pass --------------
    for (int d = 1; d < DEPTH; ++d) {
        const u32* qc = TAB.q[d];
        for (int p = 0; p < 2; ++p) {
            u32 pb = 0;
            #pragma unroll
            for (int j = 0; j < 6; ++j)
                if ((t >> j) & 1) pb ^= qc[FILL6[p][j]];
            u32 qd[6];
            #pragma unroll
            for (int k = 0; k < 6; ++k) qd[k] = qc[DIRS6[p][k]];

            float2 s[64];
            #pragma unroll
            for (int c = 0; c < 64; ++c) {
                u32 a = pb;
                if (c & 1)  a ^= qd[0];
                if (c & 2)  a ^= qd[1];
                if (c & 4)  a ^= qd[2];
                if (c & 8)  a ^= qd[3];
                if (c & 16) a ^= qd[4];
                if (c & 32) a ^= qd[5];
                s[c] = sv[a];
            }

            // ---- 6 register-resident SU(2) gates on bits p*6 .. p*6+5 ------
            #pragma unroll
            for (int g = 0; g < 6; ++g) {
                const float2* g2 = &gms[(d * NQ + DIRS6[p][g]) * 2];
                float2 u = g2[0], v = g2[1];               // m00, m01
                #pragma unroll
                for (int c = 0; c < 64; ++c) {
                    if (!((c >> g) & 1)) {
                        float2 a0 = s[c], a1 = s[c | (1 << g)];
                        float2 n0, n1;
                        n0.x = fmaf(u.x, a0.x, fmaf(-u.y, a0.y, fmaf(v.x, a1.x, -v.y * a1.y)));
                        n0.y = fmaf(u.x, a0.y, fmaf( u.y, a0.x, fmaf(v.x, a1.y,  v.y * a1.x)));
                        n1.x = fmaf(u.x, a1.x, fmaf( u.y, a1.y, fmaf(-v.x, a0.x, -v.y * a0.y)));
                        n1.y = fmaf(u.x, a1.y, fmaf(-u.y, a1.x, fmaf( v.y, a0.x, -v.x * a0.y)));
                        s[c] = n0; s[c | (1 << g)] = n1;
                    }
                }
            }

            if (d == DEPTH - 1 && p == 1) {
                // ---- fold final ring + <Z> mean into the reduction ---------
                u32 fb = 0;
                #pragma unroll
                for (int j = 0; j < 6; ++j)
                    if ((t >> j) & 1) fb ^= TAB.finv[FILL6[1][j]];
                u32 fd[6];
                #pragma unroll
                for (int k = 0; k < 6; ++k) fd[k] = TAB.finv[DIRS6[1][k]];
                #pragma unroll
                for (int c = 0; c < 64; ++c) {
                    u32 fv = fb;
                    if (c & 1)  fv ^= fd[0];
                    if (c & 2)  fv ^= fd[1];
                    if (c & 4)  fv ^= fd[2];
                    if (c & 8)  fv ^= fd[3];
                    if (c & 16) fv ^= fd[4];
                    if (c & 32) fv ^= fd[5];
                    float wgt = (float)(NQ - 2 * __popc(fv));
                    acc = fmaf(fmaf(s[c].x, s[c].x, s[c].y * s[c].y), wgt, acc);
                }
            } else {
                #pragma unroll
                for (int c = 0; c < 64; ++c) {
                    u32 a = pb;
                    if (c & 1)  a ^= qd[0];
                    if (c & 2)  a ^= qd[1];
                    if (c & 4)  a ^= qd[2];
                    if (c & 8)  a ^= qd[3];
                    if (c & 16) a ^= qd[4];
                    if (c & 32) a ^= qd[5];
                    sv[a] = s[c];
                }
                __syncthreads();
            }
        }
    }

    // ---- block reduction -> out[bid] ----
    #pragma unroll
    for (int o = 16; o; o >>= 1) acc += __shfl_xor_sync(0xffffffffu, acc, o);
    if ((t & 31) == 0) red[t >> 5] = acc;
    __syncthreads();
    if (t == 0)
        out[bid] = (red[0] + red[1]) * (1.0f / NQ);
}

extern "C" void kernel_launch(void* const* d_in, const int* in_sizes, int n_in,
                              void* d_out, int out_size)
{
    const float *inp, *wp;
    if (in_sizes[0] == DEPTH * NQ * 3) {            // defensive input-order check
        wp  = (const float*)d_in[0];
        inp = (const float*)d_in[1];
    } else {
        inp = (const float*)d_in[0];
        wp  = (const float*)d_in[1];
    }
    cudaFuncSetAttribute(qsim_kernel,
                         cudaFuncAttributePreferredSharedMemoryCarveout, 100);
    int B = out_size;                                // [B,1] float output
    qsim_kernel<<<B, TPB>>>(inp, wp, (float*)d_out);
}